// round 5
// baseline (speedup 1.0000x reference)
#include <cuda_runtime.h>
#include <math.h>
#include <float.h>
#include <stdint.h>

#define BATCH 32
#define SEQ   32
#define KB    4
#define VOCAB 32000
#define DIM   512
#define ROWS  (BATCH*KB)        // 128
#define BIGNEG (-1.0e9f)
#define END_ID 2

// ---------------- device state (no dynamic allocation allowed) ----------------
__device__ __align__(16) float g_logits[ROWS * VOCAB];   // 16.4 MB scratch
__device__ __align__(16) float g_emb[ROWS * DIM];        // A matrix for the step GEMM
__device__ int   g_tgt[ROWS * SEQ];
__device__ int   g_out[ROWS * SEQ];
__device__ float g_logp[ROWS];
__device__ float g_score[ROWS];
__device__ int   g_flag[ROWS];
__device__ float g_m[ROWS];     // per-row max
__device__ float g_ls[ROWS];    // per-row log-sum-exp (of shifted)

// ---------------- init: tgt/out = tile(x), logp/score/flag, emb for step 1 ----
__global__ void init_kernel(const float* __restrict__ ctx, const float* __restrict__ E,
                            const int* __restrict__ x) {
    int row = blockIdx.x;              // 0..127
    int b = row / KB, k = row % KB;
    int tid = threadIdx.x;             // 128
    if (tid < SEQ) {
        int t = x[b * SEQ + tid];
        g_tgt[row * SEQ + tid] = t;
        g_out[row * SEQ + tid] = t;
    }
    if (tid == 0) {
        g_logp[row]  = (k == 0) ? 0.0f : BIGNEG;
        g_score[row] = BIGNEG;
        g_flag[row]  = 0;
    }
    int tok0 = x[b * SEQ];             // prev token for step i=1 is tgt[:,:,0] = x[:,0]
    for (int d = tid; d < DIM; d += blockDim.x)
        g_emb[row * DIM + d] = E[(size_t)tok0 * DIM + d] + ctx[b * DIM + d];
}

// ---------------- GEMM: logits[128,32000] = emb[128,512] x W[512,32000] -------
// Strict serial-K ascending, single fp32 FMA accumulator per output element:
// bitwise-matches cuBLAS SGEMM / Eigen accumulation order.
// BM=64, BN=128, BK=16, 128 threads, 8x8 per-thread microtile. grid (250, 2).
__global__ void __launch_bounds__(128) gemm_kernel(const float* __restrict__ W) {
    const int v0 = blockIdx.x * 128;
    const int r0 = blockIdx.y * 64;
    __shared__ __align__(16) float As[16][64];
    __shared__ __align__(16) float Bs[16][128];
    const int tid = threadIdx.x;
    const int tr = tid >> 4, tc = tid & 15;
    const int m0 = tr * 8, n0 = tc * 8;

    float acc[8][8];
#pragma unroll
    for (int a = 0; a < 8; a++)
#pragma unroll
        for (int q = 0; q < 8; q++) acc[a][q] = 0.0f;

    const int am = tid >> 1;                 // 0..63
    const int ak = (tid & 1) * 8;            // 0 or 8
    const float* Aptr = g_emb + (size_t)(r0 + am) * DIM + ak;

    for (int k0 = 0; k0 < DIM; k0 += 16) {
        float4 a0 = *(const float4*)(Aptr + k0);
        float4 a1 = *(const float4*)(Aptr + k0 + 4);
        As[ak+0][am] = a0.x; As[ak+1][am] = a0.y; As[ak+2][am] = a0.z; As[ak+3][am] = a0.w;
        As[ak+4][am] = a1.x; As[ak+5][am] = a1.y; As[ak+6][am] = a1.z; As[ak+7][am] = a1.w;
#pragma unroll
        for (int q = 0; q < 4; q++) {
            int slot = tid + 128 * q;        // 0..511
            int bk = slot >> 5;              // 0..15
            int bn = (slot & 31) * 4;        // 0..124 step 4
            *(float4*)&Bs[bk][bn] = *(const float4*)(W + (size_t)(k0 + bk) * VOCAB + v0 + bn);
        }
        __syncthreads();
#pragma unroll
        for (int kk = 0; kk < 16; kk++) {
            float af[8], bf[8];
            *(float4*)(af)     = *(const float4*)&As[kk][m0];
            *(float4*)(af + 4) = *(const float4*)&As[kk][m0 + 4];
            *(float4*)(bf)     = *(const float4*)&Bs[kk][n0];
            *(float4*)(bf + 4) = *(const float4*)&Bs[kk][n0 + 4];
#pragma unroll
            for (int a = 0; a < 8; a++)
#pragma unroll
                for (int q = 0; q < 8; q++)
                    acc[a][q] = fmaf(af[a], bf[q], acc[a][q]);
        }
        __syncthreads();
    }
#pragma unroll
    for (int a = 0; a < 8; a++) {
        float* cp = g_logits + (size_t)(r0 + m0 + a) * VOCAB + v0 + n0;
        *(float4*)cp       = make_float4(acc[a][0], acc[a][1], acc[a][2], acc[a][3]);
        *(float4*)(cp + 4) = make_float4(acc[a][4], acc[a][5], acc[a][6], acc[a][7]);
    }
}

// ---------------- lse: replicate XLA-GPU row-reduction bitwise ----------------
// 1024 threads/row. max (exact, order-free). Then: per-thread strided ascending
// fp32 sum of expf(x-m); intra-warp shfl_down 16/8/4/2/1; per-warp partials in
// smem; warp 0 runs the same shfl tree over the 32 partials; ls = logf(total).
__global__ void __launch_bounds__(1024) lse_kernel() {
    const int row = blockIdx.x;
    const int tid = threadIdx.x;
    const int lane = tid & 31, wid = tid >> 5;
    const float* L = g_logits + (size_t)row * VOCAB;

    __shared__ float swarp[32];
    __shared__ float s_m;

    // exact max (order-independent)
    float m = -FLT_MAX;
    for (int v = tid; v < VOCAB; v += 1024) m = fmaxf(m, L[v]);
#pragma unroll
    for (int off = 16; off > 0; off >>= 1)
        m = fmaxf(m, __shfl_down_sync(0xffffffffu, m, off));
    if (lane == 0) swarp[wid] = m;
    __syncthreads();
    if (wid == 0) {
        float t = swarp[lane];
#pragma unroll
        for (int off = 16; off > 0; off >>= 1)
            t = fmaxf(t, __shfl_down_sync(0xffffffffu, t, off));
        if (lane == 0) s_m = t;
    }
    __syncthreads();
    m = s_m;

    // XLA-order sum: thread t accumulates v = t, t+1024, ... ascending, init 0.
    float s = 0.0f;
    for (int v = tid; v < VOCAB; v += 1024) s += expf(L[v] - m);
#pragma unroll
    for (int off = 16; off > 0; off >>= 1)
        s += __shfl_down_sync(0xffffffffu, s, off);
    if (lane == 0) swarp[wid] = s;
    __syncthreads();
    if (wid == 0) {
        float t = swarp[lane];
#pragma unroll
        for (int off = 16; off > 0; off >>= 1)
            t += __shfl_down_sync(0xffffffffu, t, off);
        if (lane == 0) { g_m[row] = m; g_ls[row] = logf(t); }
    }
}

// ---------------- select: rank by y = fp32(logp + fp32((x-m)-ls)) bitwise -----
// One block per batch (32 blocks, 256 threads).
__global__ void __launch_bounds__(256) select_kernel(int i, const float* __restrict__ ctx,
                                                     const float* __restrict__ E) {
    const int b = blockIdx.x;
    const int tid = threadIdx.x;

    __shared__ float  s_tval[2048];
    __shared__ int    s_tidx[2048];
    __shared__ float  s_wv[8];  __shared__ int s_wi[8];
    __shared__ float  s_cval[KB * 8]; __shared__ int s_cv[KB * 8];
    __shared__ int    s_oldtgt[KB * SEQ];
    __shared__ int    s_winner;
    __shared__ int    s_ka_beam[KB], s_ka_tok[KB], s_kf_beam[KB], s_kf_tok[KB], s_nflag[KB];
    __shared__ float  s_nlogp[KB], s_nscore[KB];

    if (tid < KB * SEQ) s_oldtgt[tid] = g_tgt[(b * KB) * SEQ + tid];

    for (int k = 0; k < KB; k++) {
        const int row = b * KB + k;
        const float* L = g_logits + (size_t)row * VOCAB;
        const float m  = g_m[row];
        const float ls = g_ls[row];
        const float lp = g_logp[row];

        // per-thread top-8 on y = lp + ((x - m) - ls); ties keep lower v
        float tv[8]; int ti[8];
#pragma unroll
        for (int j = 0; j < 8; j++) { tv[j] = -FLT_MAX; ti[j] = 0x7fffffff; }
        for (int v = tid; v < VOCAB; v += 256) {
            float sl = (L[v] - m) - ls;
            float y  = lp + sl;
            if (y > tv[7]) {
                float cv = y; int ci = v;
#pragma unroll
                for (int j = 0; j < 8; j++) {
                    if (cv > tv[j]) {
                        float tmpv = tv[j]; int tmpi = ti[j];
                        tv[j] = cv; ti[j] = ci; cv = tmpv; ci = tmpi;
                    }
                }
            }
        }

        // merge per-thread top8 -> row top8 (8 argmax rounds, ties -> low idx)
        __syncthreads();
#pragma unroll
        for (int j = 0; j < 8; j++) { s_tval[tid * 8 + j] = tv[j]; s_tidx[tid * 8 + j] = ti[j]; }
        __syncthreads();
        for (int r = 0; r < 8; r++) {
            float bv = -FLT_MAX; int bi = 0x7fffffff;
#pragma unroll
            for (int j = 0; j < 8; j++) {
                float vv = s_tval[tid * 8 + j]; int ii = s_tidx[tid * 8 + j];
                if (vv > bv || (vv == bv && ii < bi)) { bv = vv; bi = ii; }
            }
            for (int off = 16; off > 0; off >>= 1) {
                float ov = __shfl_down_sync(0xffffffffu, bv, off);
                int   oi = __shfl_down_sync(0xffffffffu, bi, off);
                if (ov > bv || (ov == bv && oi < bi)) { bv = ov; bi = oi; }
            }
            if ((tid & 31) == 0) { s_wv[tid >> 5] = bv; s_wi[tid >> 5] = bi; }
            __syncthreads();
            if (tid == 0) {
                float WV = s_wv[0]; int WI = s_wi[0];
                for (int w = 1; w < 8; w++)
                    if (s_wv[w] > WV || (s_wv[w] == WV && s_wi[w] < WI)) { WV = s_wv[w]; WI = s_wi[w]; }
                s_cval[k * 8 + r] = WV; s_cv[k * 8 + r] = WI; s_winner = WI;
            }
            __syncthreads();
#pragma unroll
            for (int j = 0; j < 8; j++)
                if (s_tidx[tid * 8 + j] == s_winner) s_tval[tid * 8 + j] = -FLT_MAX;
        }
        __syncthreads();
    }

    // --- combine 4x8 candidates + beam bookkeeping (scalar, thread 0) ---
    if (tid == 0) {
        float yv[KB * 8]; int fi[KB * 8];
        for (int k = 0; k < KB; k++) {
            for (int r = 0; r < 8; r++) {
                int idx = k * 8 + r;
                yv[idx] = s_cval[idx];               // already y = fp32(lp + sl)
                fi[idx] = k * VOCAB + s_cv[idx];
            }
        }
        float lp2k[8]; int beam8[8], tok8[8];
        bool used[KB * 8];
        for (int j = 0; j < KB * 8; j++) used[j] = false;
        for (int r = 0; r < 8; r++) {                 // global top-8, ties -> lowest flat idx
            int best = -1;
            for (int j = 0; j < KB * 8; j++) {
                if (used[j]) continue;
                if (best < 0 || yv[j] > yv[best] || (yv[j] == yv[best] && fi[j] < fi[best]))
                    best = j;
            }
            used[best] = true;
            lp2k[r] = yv[best];
            beam8[r] = fi[best] / VOCAB;
            tok8[r]  = fi[best] % VOCAB;
        }
        float n = (float)(i + 1);
        float pen = powf((5.0f + n) / 6.0f, 0.6f);
        float lpa[8], sc[8]; int fin8[8];
        for (int j = 0; j < 8; j++) {
            fin8[j] = (tok8[j] == END_ID) ? 1 : 0;
            float finf = fin8[j] ? 1.0f : 0.0f;
            lpa[j] = lp2k[j] + finf * BIGNEG;                 // mirrors lp2k + finf*BIG_NEG
            sc[j]  = lp2k[j] / pen + (1.0f - finf) * BIGNEG;  // mirrors sc formula
        }
        bool u2[8] = {false, false, false, false, false, false, false, false};
        for (int r = 0; r < KB; r++) {                // top-K alive (ties -> lower position)
            int best = -1;
            for (int j = 0; j < 8; j++)
                if (!u2[j] && (best < 0 || lpa[j] > lpa[best])) best = j;
            u2[best] = true;
            s_ka_beam[r] = beam8[best]; s_ka_tok[r] = tok8[best]; s_nlogp[r] = lpa[best];
        }
        bool u3[8] = {false, false, false, false, false, false, false, false};
        for (int r = 0; r < KB; r++) {                // top-K finished by score
            int best = -1;
            for (int j = 0; j < 8; j++)
                if (!u3[j] && (best < 0 || sc[j] > sc[best])) best = j;
            u3[best] = true;
            s_kf_beam[r] = beam8[best]; s_kf_tok[r] = tok8[best];
            s_nscore[r] = sc[best]; s_nflag[r] = fin8[best];
        }
    }
    __syncthreads();

    // --- write new tgt / out / scalars ---
    if (tid < 128) {
        int r = tid >> 5, t = tid & 31;
        int src = s_ka_beam[r];
        g_tgt[(b * KB + r) * SEQ + t] = (t == i) ? s_ka_tok[r] : s_oldtgt[src * SEQ + t];
    } else {
        int q = tid - 128;
        int r = q >> 5, t = q & 31;
        int src = s_kf_beam[r];
        g_out[(b * KB + r) * SEQ + t] = (t == i) ? s_kf_tok[r] : s_oldtgt[src * SEQ + t];
    }
    if (tid < KB) {
        g_logp[b * KB + tid]  = s_nlogp[tid];
        g_score[b * KB + tid] = s_nscore[tid];
        g_flag[b * KB + tid]  = s_nflag[tid];
    }
    // --- embeddings for the next step: prev token = token written at column i ---
    for (int idx = tid; idx < KB * DIM; idx += 256) {
        int r = idx >> 9, d = idx & (DIM - 1);
        g_emb[(size_t)(b * KB + r) * DIM + d] =
            E[(size_t)s_ka_tok[r] * DIM + d] + ctx[b * DIM + d];
    }
}

// ---------------- final: where(any_fin, out/score, tgt/logp) -> d_out ---------
__global__ void final_kernel(float* __restrict__ outp, int write_tok, int sc_off) {
    int b = blockIdx.x, tid = threadIdx.x;   // 128 threads
    __shared__ int anyfin;
    if (tid == 0)
        anyfin = g_flag[b*KB] | g_flag[b*KB+1] | g_flag[b*KB+2] | g_flag[b*KB+3];
    __syncthreads();
    int r = tid >> 5, t = tid & 31;
    int row = b * KB + r;
    if (write_tok) {
        int tok = anyfin ? g_out[row * SEQ + t] : g_tgt[row * SEQ + t];
        outp[row * SEQ + t] = (float)tok;
    }
    if (sc_off >= 0 && tid < KB)
        outp[sc_off + b * KB + tid] = anyfin ? g_score[b * KB + tid] : g_logp[b * KB + tid];
}

// ---------------- launch ------------------------------------------------------
extern "C" void kernel_launch(void* const* d_in, const int* in_sizes, int n_in,
                              void* d_out, int out_size) {
    const float* ctx = (const float*)d_in[0];
    const float* E   = (const float*)d_in[1];
    const float* W   = (const float*)d_in[2];
    const int*   x   = (const int*)d_in[3];
    (void)in_sizes; (void)n_in;

    init_kernel<<<ROWS, 128>>>(ctx, E, x);
    for (int i = 1; i < SEQ; i++) {
        gemm_kernel<<<dim3(VOCAB / 128, 2), 128>>>(W);
        lse_kernel<<<ROWS, 1024>>>();
        select_kernel<<<BATCH, 256>>>(i, ctx, E);
    }
    int write_tok = 1, sc_off = ROWS * SEQ;
    if (out_size < ROWS * SEQ + ROWS) {
        if (out_size >= ROWS * SEQ) { sc_off = -1; }          // tokens only
        else { write_tok = 0; sc_off = 0; }                    // scores only
    }
    final_kernel<<<BATCH, 128>>>((float*)d_out, write_tok, sc_off);
}

// round 6
// speedup vs baseline: 1.0038x; 1.0038x over previous
#include <cuda_runtime.h>
#include <math.h>
#include <float.h>
#include <stdint.h>

#define BATCH 32
#define SEQ   32
#define KB    4
#define VOCAB 32000
#define DIM   512
#define ROWS  (BATCH*KB)        // 128
#define BIGNEG (-1.0e9f)
#define END_ID 2

// ---------------- device state (no dynamic allocation allowed) ----------------
__device__ __align__(16) float g_logits[ROWS * VOCAB];   // 16.4 MB scratch
__device__ __align__(16) float g_emb[ROWS * DIM];        // A matrix for the step GEMM
__device__ int   g_tgt[ROWS * SEQ];
__device__ int   g_out[ROWS * SEQ];
__device__ float g_logp[ROWS];
__device__ float g_score[ROWS];
__device__ int   g_flag[ROWS];
__device__ float g_m[ROWS];     // per-row max
__device__ float g_ls[ROWS];    // per-row log-sum-exp (of shifted)

// ---------------- init: tgt/out = tile(x), logp/score/flag, emb for step 1 ----
__global__ void init_kernel(const float* __restrict__ ctx, const float* __restrict__ E,
                            const int* __restrict__ x) {
    int row = blockIdx.x;              // 0..127
    int b = row / KB, k = row % KB;
    int tid = threadIdx.x;             // 128
    if (tid < SEQ) {
        int t = x[b * SEQ + tid];
        g_tgt[row * SEQ + tid] = t;
        g_out[row * SEQ + tid] = t;
    }
    if (tid == 0) {
        g_logp[row]  = (k == 0) ? 0.0f : BIGNEG;
        g_score[row] = BIGNEG;
        g_flag[row]  = 0;
    }
    int tok0 = x[b * SEQ];             // prev token for step i=1 is tgt[:,:,0] = x[:,0]
    for (int d = tid; d < DIM; d += blockDim.x)
        g_emb[row * DIM + d] = E[(size_t)tok0 * DIM + d] + ctx[b * DIM + d];
}

// ---------------- GEMM: logits[128,32000] = emb[128,512] x W[512,32000] -------
// Strict serial-K ascending, single fp32 FMA accumulator per output element:
// bitwise-matches cuBLAS SGEMM / Eigen accumulation order.
// BM=64, BN=128, BK=16, 128 threads, 8x8 per-thread microtile. grid (250, 2).
__global__ void __launch_bounds__(128) gemm_kernel(const float* __restrict__ W) {
    const int v0 = blockIdx.x * 128;
    const int r0 = blockIdx.y * 64;
    __shared__ __align__(16) float As[16][64];
    __shared__ __align__(16) float Bs[16][128];
    const int tid = threadIdx.x;
    const int tr = tid >> 4, tc = tid & 15;
    const int m0 = tr * 8, n0 = tc * 8;

    float acc[8][8];
#pragma unroll
    for (int a = 0; a < 8; a++)
#pragma unroll
        for (int q = 0; q < 8; q++) acc[a][q] = 0.0f;

    const int am = tid >> 1;                 // 0..63
    const int ak = (tid & 1) * 8;            // 0 or 8
    const float* Aptr = g_emb + (size_t)(r0 + am) * DIM + ak;

    for (int k0 = 0; k0 < DIM; k0 += 16) {
        float4 a0 = *(const float4*)(Aptr + k0);
        float4 a1 = *(const float4*)(Aptr + k0 + 4);
        As[ak+0][am] = a0.x; As[ak+1][am] = a0.y; As[ak+2][am] = a0.z; As[ak+3][am] = a0.w;
        As[ak+4][am] = a1.x; As[ak+5][am] = a1.y; As[ak+6][am] = a1.z; As[ak+7][am] = a1.w;
#pragma unroll
        for (int q = 0; q < 4; q++) {
            int slot = tid + 128 * q;        // 0..511
            int bk = slot >> 5;              // 0..15
            int bn = (slot & 31) * 4;        // 0..124 step 4
            *(float4*)&Bs[bk][bn] = *(const float4*)(W + (size_t)(k0 + bk) * VOCAB + v0 + bn);
        }
        __syncthreads();
#pragma unroll
        for (int kk = 0; kk < 16; kk++) {
            float af[8], bf[8];
            *(float4*)(af)     = *(const float4*)&As[kk][m0];
            *(float4*)(af + 4) = *(const float4*)&As[kk][m0 + 4];
            *(float4*)(bf)     = *(const float4*)&Bs[kk][n0];
            *(float4*)(bf + 4) = *(const float4*)&Bs[kk][n0 + 4];
#pragma unroll
            for (int a = 0; a < 8; a++)
#pragma unroll
                for (int q = 0; q < 8; q++)
                    acc[a][q] = fmaf(af[a], bf[q], acc[a][q]);
        }
        __syncthreads();
    }
#pragma unroll
    for (int a = 0; a < 8; a++) {
        float* cp = g_logits + (size_t)(r0 + m0 + a) * VOCAB + v0 + n0;
        *(float4*)cp       = make_float4(acc[a][0], acc[a][1], acc[a][2], acc[a][3]);
        *(float4*)(cp + 4) = make_float4(acc[a][4], acc[a][5], acc[a][6], acc[a][7]);
    }
}

// ---------------- lse: replicate XLA-GPU row-reduction bitwise ----------------
// 1024 threads/row. max (exact, order-free). Then: per-thread strided ascending
// fp32 sum of expf(x-m); intra-warp shfl_down 16/8/4/2/1; per-warp partials in
// smem; warp 0 runs the same shfl tree over the 32 partials; ls = logf(total).
__global__ void __launch_bounds__(1024) lse_kernel() {
    const int row = blockIdx.x;
    const int tid = threadIdx.x;
    const int lane = tid & 31, wid = tid >> 5;
    const float* L = g_logits + (size_t)row * VOCAB;

    __shared__ float swarp[32];
    __shared__ float s_m;

    // exact max (order-independent)
    float m = -FLT_MAX;
    for (int v = tid; v < VOCAB; v += 1024) m = fmaxf(m, L[v]);
#pragma unroll
    for (int off = 16; off > 0; off >>= 1)
        m = fmaxf(m, __shfl_down_sync(0xffffffffu, m, off));
    if (lane == 0) swarp[wid] = m;
    __syncthreads();
    if (wid == 0) {
        float t = swarp[lane];
#pragma unroll
        for (int off = 16; off > 0; off >>= 1)
            t = fmaxf(t, __shfl_down_sync(0xffffffffu, t, off));
        if (lane == 0) s_m = t;
    }
    __syncthreads();
    m = s_m;

    // XLA-order sum: thread t accumulates v = t, t+1024, ... ascending, init 0.
    float s = 0.0f;
    for (int v = tid; v < VOCAB; v += 1024) s += expf(L[v] - m);
#pragma unroll
    for (int off = 16; off > 0; off >>= 1)
        s += __shfl_down_sync(0xffffffffu, s, off);
    if (lane == 0) swarp[wid] = s;
    __syncthreads();
    if (wid == 0) {
        float t = swarp[lane];
#pragma unroll
        for (int off = 16; off > 0; off >>= 1)
            t += __shfl_down_sync(0xffffffffu, t, off);
        if (lane == 0) { g_m[row] = m; g_ls[row] = logf(t); }
    }
}

// ---------------- select: rank by y = fp32(logp + fp32((x-m)-ls)) bitwise -----
// One block per batch (32 blocks, 256 threads).
__global__ void __launch_bounds__(256) select_kernel(int i, const float* __restrict__ ctx,
                                                     const float* __restrict__ E) {
    const int b = blockIdx.x;
    const int tid = threadIdx.x;

    __shared__ float  s_tval[2048];
    __shared__ int    s_tidx[2048];
    __shared__ float  s_wv[8];  __shared__ int s_wi[8];
    __shared__ float  s_cval[KB * 8]; __shared__ int s_cv[KB * 8];
    __shared__ int    s_oldtgt[KB * SEQ];
    __shared__ int    s_winner;
    __shared__ int    s_ka_beam[KB], s_ka_tok[KB], s_kf_beam[KB], s_kf_tok[KB], s_nflag[KB];
    __shared__ float  s_nlogp[KB], s_nscore[KB];

    if (tid < KB * SEQ) s_oldtgt[tid] = g_tgt[(b * KB) * SEQ + tid];

    for (int k = 0; k < KB; k++) {
        const int row = b * KB + k;
        const float* L = g_logits + (size_t)row * VOCAB;
        const float m  = g_m[row];
        const float ls = g_ls[row];
        const float lp = g_logp[row];

        // per-thread top-8 on y = lp + ((x - m) - ls); ties keep lower v
        float tv[8]; int ti[8];
#pragma unroll
        for (int j = 0; j < 8; j++) { tv[j] = -FLT_MAX; ti[j] = 0x7fffffff; }
        for (int v = tid; v < VOCAB; v += 256) {
            float sl = (L[v] - m) - ls;
            float y  = lp + sl;
            if (y > tv[7]) {
                float cv = y; int ci = v;
#pragma unroll
                for (int j = 0; j < 8; j++) {
                    if (cv > tv[j]) {
                        float tmpv = tv[j]; int tmpi = ti[j];
                        tv[j] = cv; ti[j] = ci; cv = tmpv; ci = tmpi;
                    }
                }
            }
        }

        // merge per-thread top8 -> row top8 (8 argmax rounds, ties -> low idx)
        __syncthreads();
#pragma unroll
        for (int j = 0; j < 8; j++) { s_tval[tid * 8 + j] = tv[j]; s_tidx[tid * 8 + j] = ti[j]; }
        __syncthreads();
        for (int r = 0; r < 8; r++) {
            float bv = -FLT_MAX; int bi = 0x7fffffff;
#pragma unroll
            for (int j = 0; j < 8; j++) {
                float vv = s_tval[tid * 8 + j]; int ii = s_tidx[tid * 8 + j];
                if (vv > bv || (vv == bv && ii < bi)) { bv = vv; bi = ii; }
            }
            for (int off = 16; off > 0; off >>= 1) {
                float ov = __shfl_down_sync(0xffffffffu, bv, off);
                int   oi = __shfl_down_sync(0xffffffffu, bi, off);
                if (ov > bv || (ov == bv && oi < bi)) { bv = ov; bi = oi; }
            }
            if ((tid & 31) == 0) { s_wv[tid >> 5] = bv; s_wi[tid >> 5] = bi; }
            __syncthreads();
            if (tid == 0) {
                float WV = s_wv[0]; int WI = s_wi[0];
                for (int w = 1; w < 8; w++)
                    if (s_wv[w] > WV || (s_wv[w] == WV && s_wi[w] < WI)) { WV = s_wv[w]; WI = s_wi[w]; }
                s_cval[k * 8 + r] = WV; s_cv[k * 8 + r] = WI; s_winner = WI;
            }
            __syncthreads();
#pragma unroll
            for (int j = 0; j < 8; j++)
                if (s_tidx[tid * 8 + j] == s_winner) s_tval[tid * 8 + j] = -FLT_MAX;
        }
        __syncthreads();
    }

    // --- combine 4x8 candidates + beam bookkeeping (scalar, thread 0) ---
    if (tid == 0) {
        float yv[KB * 8]; int fi[KB * 8];
        for (int k = 0; k < KB; k++) {
            for (int r = 0; r < 8; r++) {
                int idx = k * 8 + r;
                yv[idx] = s_cval[idx];               // already y = fp32(lp + sl)
                fi[idx] = k * VOCAB + s_cv[idx];
            }
        }
        float lp2k[8]; int beam8[8], tok8[8];
        bool used[KB * 8];
        for (int j = 0; j < KB * 8; j++) used[j] = false;
        for (int r = 0; r < 8; r++) {                 // global top-8, ties -> lowest flat idx
            int best = -1;
            for (int j = 0; j < KB * 8; j++) {
                if (used[j]) continue;
                if (best < 0 || yv[j] > yv[best] || (yv[j] == yv[best] && fi[j] < fi[best]))
                    best = j;
            }
            used[best] = true;
            lp2k[r] = yv[best];
            beam8[r] = fi[best] / VOCAB;
            tok8[r]  = fi[best] % VOCAB;
        }
        float n = (float)(i + 1);
        float pen = powf((5.0f + n) / 6.0f, 0.6f);
        float lpa[8], sc[8]; int fin8[8];
        for (int j = 0; j < 8; j++) {
            fin8[j] = (tok8[j] == END_ID) ? 1 : 0;
            float finf = fin8[j] ? 1.0f : 0.0f;
            lpa[j] = lp2k[j] + finf * BIGNEG;                 // mirrors lp2k + finf*BIG_NEG
            sc[j]  = lp2k[j] / pen + (1.0f - finf) * BIGNEG;  // mirrors sc formula
        }
        bool u2[8] = {false, false, false, false, false, false, false, false};
        for (int r = 0; r < KB; r++) {                // top-K alive (ties -> lower position)
            int best = -1;
            for (int j = 0; j < 8; j++)
                if (!u2[j] && (best < 0 || lpa[j] > lpa[best])) best = j;
            u2[best] = true;
            s_ka_beam[r] = beam8[best]; s_ka_tok[r] = tok8[best]; s_nlogp[r] = lpa[best];
        }
        bool u3[8] = {false, false, false, false, false, false, false, false};
        for (int r = 0; r < KB; r++) {                // top-K finished by score
            int best = -1;
            for (int j = 0; j < 8; j++)
                if (!u3[j] && (best < 0 || sc[j] > sc[best])) best = j;
            u3[best] = true;
            s_kf_beam[r] = beam8[best]; s_kf_tok[r] = tok8[best];
            s_nscore[r] = sc[best]; s_nflag[r] = fin8[best];
        }
    }
    __syncthreads();

    // --- write new tgt / out / scalars ---
    if (tid < 128) {
        int r = tid >> 5, t = tid & 31;
        int src = s_ka_beam[r];
        g_tgt[(b * KB + r) * SEQ + t] = (t == i) ? s_ka_tok[r] : s_oldtgt[src * SEQ + t];
    } else {
        int q = tid - 128;
        int r = q >> 5, t = q & 31;
        int src = s_kf_beam[r];
        g_out[(b * KB + r) * SEQ + t] = (t == i) ? s_kf_tok[r] : s_oldtgt[src * SEQ + t];
    }
    if (tid < KB) {
        g_logp[b * KB + tid]  = s_nlogp[tid];
        g_score[b * KB + tid] = s_nscore[tid];
        g_flag[b * KB + tid]  = s_nflag[tid];
    }
    // --- embeddings for the next step: prev token = token written at column i ---
    for (int idx = tid; idx < KB * DIM; idx += 256) {
        int r = idx >> 9, d = idx & (DIM - 1);
        g_emb[(size_t)(b * KB + r) * DIM + d] =
            E[(size_t)s_ka_tok[r] * DIM + d] + ctx[b * DIM + d];
    }
}

// ---------------- final: where(any_fin, out/score, tgt/logp) -> d_out ---------
__global__ void final_kernel(float* __restrict__ outp, int write_tok, int sc_off) {
    int b = blockIdx.x, tid = threadIdx.x;   // 128 threads
    __shared__ int anyfin;
    if (tid == 0)
        anyfin = g_flag[b*KB] | g_flag[b*KB+1] | g_flag[b*KB+2] | g_flag[b*KB+3];
    __syncthreads();
    int r = tid >> 5, t = tid & 31;
    int row = b * KB + r;
    if (write_tok) {
        int tok = anyfin ? g_out[row * SEQ + t] : g_tgt[row * SEQ + t];
        outp[row * SEQ + t] = (float)tok;
    }
    if (sc_off >= 0 && tid < KB)
        outp[sc_off + b * KB + tid] = anyfin ? g_score[b * KB + tid] : g_logp[b * KB + tid];
}

// ---------------- launch ------------------------------------------------------
extern "C" void kernel_launch(void* const* d_in, const int* in_sizes, int n_in,
                              void* d_out, int out_size) {
    const float* ctx = (const float*)d_in[0];
    const float* E   = (const float*)d_in[1];
    const float* W   = (const float*)d_in[2];
    const int*   x   = (const int*)d_in[3];
    (void)in_sizes; (void)n_in;

    init_kernel<<<ROWS, 128>>>(ctx, E, x);
    for (int i = 1; i < SEQ; i++) {
        gemm_kernel<<<dim3(VOCAB / 128, 2), 128>>>(W);
        lse_kernel<<<ROWS, 1024>>>();
        select_kernel<<<BATCH, 256>>>(i, ctx, E);
    }
    int write_tok = 1, sc_off = ROWS * SEQ;
    if (out_size < ROWS * SEQ + ROWS) {
        if (out_size >= ROWS * SEQ) { sc_off = -1; }          // tokens only
        else { write_tok = 0; sc_off = 0; }                    // scores only
    }
    final_kernel<<<BATCH, 128>>>((float*)d_out, write_tok, sc_off);
}

// round 7
// speedup vs baseline: 1.0073x; 1.0035x over previous
#include <cuda_runtime.h>
#include <math.h>
#include <float.h>
#include <stdint.h>

#define BATCH 32
#define SEQ   32
#define KB    4
#define VOCAB 32000
#define DIM   512
#define ROWS  (BATCH*KB)        // 128
#define BIGNEG (-1.0e9f)
#define END_ID 2

// ---------------- device state (no dynamic allocation allowed) ----------------
__device__ __align__(16) float g_logits[ROWS * VOCAB];   // 16.4 MB scratch
__device__ __align__(16) float g_emb[ROWS * DIM];        // A matrix for the step GEMM
__device__ int   g_tgt[ROWS * SEQ];
__device__ int   g_out[ROWS * SEQ];
__device__ float g_logp[ROWS];
__device__ float g_score[ROWS];
__device__ int   g_flag[ROWS];
__device__ float g_m[ROWS];     // per-row max
__device__ float g_ls[ROWS];    // per-row log-sum-exp (of shifted)

// ---------------- init: tgt/out = tile(x), logp/score/flag, emb for step 1 ----
__global__ void init_kernel(const float* __restrict__ ctx, const float* __restrict__ E,
                            const int* __restrict__ x) {
    int row = blockIdx.x;              // 0..127
    int b = row / KB, k = row % KB;
    int tid = threadIdx.x;             // 128
    if (tid < SEQ) {
        int t = x[b * SEQ + tid];
        g_tgt[row * SEQ + tid] = t;
        g_out[row * SEQ + tid] = t;
    }
    if (tid == 0) {
        g_logp[row]  = (k == 0) ? 0.0f : BIGNEG;
        g_score[row] = BIGNEG;
        g_flag[row]  = 0;
    }
    int tok0 = x[b * SEQ];             // prev token for step i=1 is tgt[:,:,0] = x[:,0]
    for (int d = tid; d < DIM; d += blockDim.x)
        g_emb[row * DIM + d] = E[(size_t)tok0 * DIM + d] + ctx[b * DIM + d];
}

// ---------------- GEMM: logits[128,32000] = emb[128,512] x W[512,32000] -------
// Strict serial-K ascending, single fp32 FMA accumulator per output element:
// bitwise-matches cuBLAS SGEMM / Eigen accumulation order.
// BM=64, BN=128, BK=16, 128 threads, 8x8 per-thread microtile. grid (250, 2).
__global__ void __launch_bounds__(128) gemm_kernel(const float* __restrict__ W) {
    const int v0 = blockIdx.x * 128;
    const int r0 = blockIdx.y * 64;
    __shared__ __align__(16) float As[16][64];
    __shared__ __align__(16) float Bs[16][128];
    const int tid = threadIdx.x;
    const int tr = tid >> 4, tc = tid & 15;
    const int m0 = tr * 8, n0 = tc * 8;

    float acc[8][8];
#pragma unroll
    for (int a = 0; a < 8; a++)
#pragma unroll
        for (int q = 0; q < 8; q++) acc[a][q] = 0.0f;

    const int am = tid >> 1;                 // 0..63
    const int ak = (tid & 1) * 8;            // 0 or 8
    const float* Aptr = g_emb + (size_t)(r0 + am) * DIM + ak;

    for (int k0 = 0; k0 < DIM; k0 += 16) {
        float4 a0 = *(const float4*)(Aptr + k0);
        float4 a1 = *(const float4*)(Aptr + k0 + 4);
        As[ak+0][am] = a0.x; As[ak+1][am] = a0.y; As[ak+2][am] = a0.z; As[ak+3][am] = a0.w;
        As[ak+4][am] = a1.x; As[ak+5][am] = a1.y; As[ak+6][am] = a1.z; As[ak+7][am] = a1.w;
#pragma unroll
        for (int q = 0; q < 4; q++) {
            int slot = tid + 128 * q;        // 0..511
            int bk = slot >> 5;              // 0..15
            int bn = (slot & 31) * 4;        // 0..124 step 4
            *(float4*)&Bs[bk][bn] = *(const float4*)(W + (size_t)(k0 + bk) * VOCAB + v0 + bn);
        }
        __syncthreads();
#pragma unroll
        for (int kk = 0; kk < 16; kk++) {
            float af[8], bf[8];
            *(float4*)(af)     = *(const float4*)&As[kk][m0];
            *(float4*)(af + 4) = *(const float4*)&As[kk][m0 + 4];
            *(float4*)(bf)     = *(const float4*)&Bs[kk][n0];
            *(float4*)(bf + 4) = *(const float4*)&Bs[kk][n0 + 4];
#pragma unroll
            for (int a = 0; a < 8; a++)
#pragma unroll
                for (int q = 0; q < 8; q++)
                    acc[a][q] = fmaf(af[a], bf[q], acc[a][q]);
        }
        __syncthreads();
    }
#pragma unroll
    for (int a = 0; a < 8; a++) {
        float* cp = g_logits + (size_t)(r0 + m0 + a) * VOCAB + v0 + n0;
        *(float4*)cp       = make_float4(acc[a][0], acc[a][1], acc[a][2], acc[a][3]);
        *(float4*)(cp + 4) = make_float4(acc[a][4], acc[a][5], acc[a][6], acc[a][7]);
    }
}

// ---------------- lse: replicate XLA-GPU row-reduction bitwise ----------------
// 1024 threads/row. max (exact, order-free). Then: per-thread strided ascending
// fp32 sum of expf(x-m); intra-warp shfl_down 16/8/4/2/1; per-warp partials in
// smem; warp 0 runs the same shfl tree over the 32 partials; ls = logf(total).
__global__ void __launch_bounds__(1024) lse_kernel() {
    const int row = blockIdx.x;
    const int tid = threadIdx.x;
    const int lane = tid & 31, wid = tid >> 5;
    const float* L = g_logits + (size_t)row * VOCAB;

    __shared__ float swarp[32];
    __shared__ float s_m;

    // exact max (order-independent)
    float m = -FLT_MAX;
    for (int v = tid; v < VOCAB; v += 1024) m = fmaxf(m, L[v]);
#pragma unroll
    for (int off = 16; off > 0; off >>= 1)
        m = fmaxf(m, __shfl_down_sync(0xffffffffu, m, off));
    if (lane == 0) swarp[wid] = m;
    __syncthreads();
    if (wid == 0) {
        float t = swarp[lane];
#pragma unroll
        for (int off = 16; off > 0; off >>= 1)
            t = fmaxf(t, __shfl_down_sync(0xffffffffu, t, off));
        if (lane == 0) s_m = t;
    }
    __syncthreads();
    m = s_m;

    // XLA-order sum: thread t accumulates v = t, t+1024, ... ascending, init 0.
    float s = 0.0f;
    for (int v = tid; v < VOCAB; v += 1024) s += expf(L[v] - m);
#pragma unroll
    for (int off = 16; off > 0; off >>= 1)
        s += __shfl_down_sync(0xffffffffu, s, off);
    if (lane == 0) swarp[wid] = s;
    __syncthreads();
    if (wid == 0) {
        float t = swarp[lane];
#pragma unroll
        for (int off = 16; off > 0; off >>= 1)
            t += __shfl_down_sync(0xffffffffu, t, off);
        if (lane == 0) { g_m[row] = m; g_ls[row] = logf(t); }
    }
}

// ---------------- select: rank by y = fp32(logp + fp32((x-m)-ls)) bitwise -----
// One block per batch (32 blocks, 256 threads).
__global__ void __launch_bounds__(256) select_kernel(int i, const float* __restrict__ ctx,
                                                     const float* __restrict__ E) {
    const int b = blockIdx.x;
    const int tid = threadIdx.x;

    __shared__ float  s_tval[2048];
    __shared__ int    s_tidx[2048];
    __shared__ float  s_wv[8];  __shared__ int s_wi[8];
    __shared__ float  s_cval[KB * 8]; __shared__ int s_cv[KB * 8];
    __shared__ int    s_oldtgt[KB * SEQ];
    __shared__ int    s_winner;
    __shared__ int    s_ka_beam[KB], s_ka_tok[KB], s_kf_beam[KB], s_kf_tok[KB], s_nflag[KB];
    __shared__ float  s_nlogp[KB], s_nscore[KB];

    if (tid < KB * SEQ) s_oldtgt[tid] = g_tgt[(b * KB) * SEQ + tid];

    for (int k = 0; k < KB; k++) {
        const int row = b * KB + k;
        const float* L = g_logits + (size_t)row * VOCAB;
        const float m  = g_m[row];
        const float ls = g_ls[row];
        const float lp = g_logp[row];

        // per-thread top-8 on y = lp + ((x - m) - ls); ties keep lower v
        float tv[8]; int ti[8];
#pragma unroll
        for (int j = 0; j < 8; j++) { tv[j] = -FLT_MAX; ti[j] = 0x7fffffff; }
        for (int v = tid; v < VOCAB; v += 256) {
            float sl = (L[v] - m) - ls;
            float y  = lp + sl;
            if (y > tv[7]) {
                float cv = y; int ci = v;
#pragma unroll
                for (int j = 0; j < 8; j++) {
                    if (cv > tv[j]) {
                        float tmpv = tv[j]; int tmpi = ti[j];
                        tv[j] = cv; ti[j] = ci; cv = tmpv; ci = tmpi;
                    }
                }
            }
        }

        // merge per-thread top8 -> row top8 (8 argmax rounds, ties -> low idx)
        __syncthreads();
#pragma unroll
        for (int j = 0; j < 8; j++) { s_tval[tid * 8 + j] = tv[j]; s_tidx[tid * 8 + j] = ti[j]; }
        __syncthreads();
        for (int r = 0; r < 8; r++) {
            float bv = -FLT_MAX; int bi = 0x7fffffff;
#pragma unroll
            for (int j = 0; j < 8; j++) {
                float vv = s_tval[tid * 8 + j]; int ii = s_tidx[tid * 8 + j];
                if (vv > bv || (vv == bv && ii < bi)) { bv = vv; bi = ii; }
            }
            for (int off = 16; off > 0; off >>= 1) {
                float ov = __shfl_down_sync(0xffffffffu, bv, off);
                int   oi = __shfl_down_sync(0xffffffffu, bi, off);
                if (ov > bv || (ov == bv && oi < bi)) { bv = ov; bi = oi; }
            }
            if ((tid & 31) == 0) { s_wv[tid >> 5] = bv; s_wi[tid >> 5] = bi; }
            __syncthreads();
            if (tid == 0) {
                float WV = s_wv[0]; int WI = s_wi[0];
                for (int w = 1; w < 8; w++)
                    if (s_wv[w] > WV || (s_wv[w] == WV && s_wi[w] < WI)) { WV = s_wv[w]; WI = s_wi[w]; }
                s_cval[k * 8 + r] = WV; s_cv[k * 8 + r] = WI; s_winner = WI;
            }
            __syncthreads();
#pragma unroll
            for (int j = 0; j < 8; j++)
                if (s_tidx[tid * 8 + j] == s_winner) s_tval[tid * 8 + j] = -FLT_MAX;
        }
        __syncthreads();
    }

    // --- combine 4x8 candidates + beam bookkeeping (scalar, thread 0) ---
    if (tid == 0) {
        float yv[KB * 8]; int fi[KB * 8];
        for (int k = 0; k < KB; k++) {
            for (int r = 0; r < 8; r++) {
                int idx = k * 8 + r;
                yv[idx] = s_cval[idx];               // already y = fp32(lp + sl)
                fi[idx] = k * VOCAB + s_cv[idx];
            }
        }
        float lp2k[8]; int beam8[8], tok8[8];
        bool used[KB * 8];
        for (int j = 0; j < KB * 8; j++) used[j] = false;
        for (int r = 0; r < 8; r++) {                 // global top-8, ties -> lowest flat idx
            int best = -1;
            for (int j = 0; j < KB * 8; j++) {
                if (used[j]) continue;
                if (best < 0 || yv[j] > yv[best] || (yv[j] == yv[best] && fi[j] < fi[best]))
                    best = j;
            }
            used[best] = true;
            lp2k[r] = yv[best];
            beam8[r] = fi[best] / VOCAB;
            tok8[r]  = fi[best] % VOCAB;
        }
        float n = (float)(i + 1);
        float pen = powf((5.0f + n) / 6.0f, 0.6f);
        float lpa[8], sc[8]; int fin8[8];
        for (int j = 0; j < 8; j++) {
            fin8[j] = (tok8[j] == END_ID) ? 1 : 0;
            float finf = fin8[j] ? 1.0f : 0.0f;
            lpa[j] = lp2k[j] + finf * BIGNEG;                 // mirrors lp2k + finf*BIG_NEG
            sc[j]  = lp2k[j] / pen + (1.0f - finf) * BIGNEG;  // mirrors sc formula
        }
        bool u2[8] = {false, false, false, false, false, false, false, false};
        for (int r = 0; r < KB; r++) {                // top-K alive (ties -> lower position)
            int best = -1;
            for (int j = 0; j < 8; j++)
                if (!u2[j] && (best < 0 || lpa[j] > lpa[best])) best = j;
            u2[best] = true;
            s_ka_beam[r] = beam8[best]; s_ka_tok[r] = tok8[best]; s_nlogp[r] = lpa[best];
        }
        bool u3[8] = {false, false, false, false, false, false, false, false};
        for (int r = 0; r < KB; r++) {                // top-K finished by score
            int best = -1;
            for (int j = 0; j < 8; j++)
                if (!u3[j] && (best < 0 || sc[j] > sc[best])) best = j;
            u3[best] = true;
            s_kf_beam[r] = beam8[best]; s_kf_tok[r] = tok8[best];
            s_nscore[r] = sc[best]; s_nflag[r] = fin8[best];
        }
    }
    __syncthreads();

    // --- write new tgt / out / scalars ---
    if (tid < 128) {
        int r = tid >> 5, t = tid & 31;
        int src = s_ka_beam[r];
        g_tgt[(b * KB + r) * SEQ + t] = (t == i) ? s_ka_tok[r] : s_oldtgt[src * SEQ + t];
    } else {
        int q = tid - 128;
        int r = q >> 5, t = q & 31;
        int src = s_kf_beam[r];
        g_out[(b * KB + r) * SEQ + t] = (t == i) ? s_kf_tok[r] : s_oldtgt[src * SEQ + t];
    }
    if (tid < KB) {
        g_logp[b * KB + tid]  = s_nlogp[tid];
        g_score[b * KB + tid] = s_nscore[tid];
        g_flag[b * KB + tid]  = s_nflag[tid];
    }
    // --- embeddings for the next step: prev token = token written at column i ---
    for (int idx = tid; idx < KB * DIM; idx += 256) {
        int r = idx >> 9, d = idx & (DIM - 1);
        g_emb[(size_t)(b * KB + r) * DIM + d] =
            E[(size_t)s_ka_tok[r] * DIM + d] + ctx[b * DIM + d];
    }
}

// ---------------- final: where(any_fin, out/score, tgt/logp) -> d_out ---------
__global__ void final_kernel(float* __restrict__ outp, int write_tok, int sc_off) {
    int b = blockIdx.x, tid = threadIdx.x;   // 128 threads
    __shared__ int anyfin;
    if (tid == 0)
        anyfin = g_flag[b*KB] | g_flag[b*KB+1] | g_flag[b*KB+2] | g_flag[b*KB+3];
    __syncthreads();
    int r = tid >> 5, t = tid & 31;
    int row = b * KB + r;
    if (write_tok) {
        int tok = anyfin ? g_out[row * SEQ + t] : g_tgt[row * SEQ + t];
        outp[row * SEQ + t] = (float)tok;
    }
    if (sc_off >= 0 && tid < KB)
        outp[sc_off + b * KB + tid] = anyfin ? g_score[b * KB + tid] : g_logp[b * KB + tid];
}

// ---------------- launch ------------------------------------------------------
extern "C" void kernel_launch(void* const* d_in, const int* in_sizes, int n_in,
                              void* d_out, int out_size) {
    const float* ctx = (const float*)d_in[0];
    const float* E   = (const float*)d_in[1];
    const float* W   = (const float*)d_in[2];
    const int*   x   = (const int*)d_in[3];
    (void)in_sizes; (void)n_in;

    init_kernel<<<ROWS, 128>>>(ctx, E, x);
    for (int i = 1; i < SEQ; i++) {
        gemm_kernel<<<dim3(VOCAB / 128, 2), 128>>>(W);
        lse_kernel<<<ROWS, 1024>>>();
        select_kernel<<<BATCH, 256>>>(i, ctx, E);
    }
    int write_tok = 1, sc_off = ROWS * SEQ;
    if (out_size < ROWS * SEQ + ROWS) {
        if (out_size >= ROWS * SEQ) { sc_off = -1; }          // tokens only
        else { write_tok = 0; sc_off = 0; }                    // scores only
    }
    final_kernel<<<BATCH, 128>>>((float*)d_out, write_tok, sc_off);
}